// round 1
// baseline (speedup 1.0000x reference)
#include <cuda_runtime.h>

#define BB 256
#define SS 2048
#define VOCAB 10
#define EE 32
#define HH 64
#define OUTD 10
#define HSTRIDE 68   // 68*4 = 272 bytes, multiple of 16 -> float4-aligned rows

__global__ __launch_bounds__(64) void rnn_fused_kernel(
    const int* __restrict__ num1, const int* __restrict__ num2,
    const float* __restrict__ embed, const float* __restrict__ Wx,
    const float* __restrict__ Wh, const float* __restrict__ b,
    const float* __restrict__ Wd, const float* __restrict__ bd,
    float* __restrict__ out)
{
    __shared__ float t1[VOCAB][HH];
    __shared__ float t2[VOCAB][HH];
    __shared__ unsigned char n1s[SS];
    __shared__ unsigned char n2s[SS];
    __shared__ __align__(16) float hist[64][HSTRIDE];
    __shared__ float wd_sh[HH][OUTD];
    __shared__ float bd_sh[OUTD];

    const int j   = threadIdx.x;   // 0..63, owns h[j]
    const int row = blockIdx.x;    // batch row

    // ---- Prologue: input-projection tables (xw has only 10+10 distinct halves) ----
    {
        float wxa[EE], wxb[EE];
        #pragma unroll
        for (int e = 0; e < EE; e++) {
            wxa[e] = Wx[e * HH + j];
            wxb[e] = Wx[(EE + e) * HH + j];
        }
        float bj = b[j];
        #pragma unroll
        for (int v = 0; v < VOCAB; v++) {
            float a1 = bj, a2 = 0.0f;
            #pragma unroll
            for (int e = 0; e < EE; e++) {
                float ev = embed[v * EE + e];   // broadcast, L1 hits
                a1 = fmaf(ev, wxa[e], a1);
                a2 = fmaf(ev, wxb[e], a2);
            }
            t1[v][j] = a1;
            t2[v][j] = a2;
        }
    }

    // ---- Wh column j into registers ----
    float wcol[HH];
    #pragma unroll
    for (int k = 0; k < HH; k++) wcol[k] = Wh[k * HH + j];  // coalesced across j

    // ---- Stage token indices as bytes in shared ----
    {
        const int* n1p = num1 + row * SS;
        const int* n2p = num2 + row * SS;
        for (int i = j; i < SS; i += HH) {
            n1s[i] = (unsigned char)n1p[i];
            n2s[i] = (unsigned char)n2p[i];
        }
    }

    // ---- Output weights to shared ----
    for (int i = j; i < HH * OUTD; i += HH) wd_sh[i / OUTD][i % OUTD] = Wd[i];
    if (j < OUTD) bd_sh[j] = bd[j];

    // h_{-1} = 0 lives in slot 63 (step s reads slot (s+63)&63)
    hist[63][j] = 0.0f;
    __syncthreads();

    float* outrow = out + (size_t)row * SS * OUTD;

    for (int s = 0; s < SS; s++) {
        const int n1 = n1s[s];
        const int n2 = n2s[s];
        float acc0 = t1[n1][j] + t2[n2][j];
        float acc1 = 0.0f, acc2 = 0.0f, acc3 = 0.0f;

        const float4* hv = (const float4*)hist[(s + 63) & 63];  // broadcast reads
        #pragma unroll
        for (int k4 = 0; k4 < 16; k4++) {
            float4 hh = hv[k4];
            acc0 = fmaf(hh.x, wcol[4 * k4 + 0], acc0);
            acc1 = fmaf(hh.y, wcol[4 * k4 + 1], acc1);
            acc2 = fmaf(hh.z, wcol[4 * k4 + 2], acc2);
            acc3 = fmaf(hh.w, wcol[4 * k4 + 3], acc3);
        }
        float z  = (acc0 + acc1) + (acc2 + acc3);
        float hn = tanhf(z);
        hist[s & 63][j] = hn;

        if ((s & 63) == 63) {
            __syncthreads();   // history window complete
            // ---- Fused output projection for steps s-63..s ----
            // Thread j handles local step j: logits = hist[j][:] @ Wd + bd
            float oacc[OUTD];
            #pragma unroll
            for (int o = 0; o < OUTD; o++) oacc[o] = bd_sh[o];
            const float* hr = hist[j];
            #pragma unroll 8
            for (int k = 0; k < HH; k++) {
                float hvv = hr[k];
                #pragma unroll
                for (int o = 0; o < OUTD; o++)
                    oacc[o] = fmaf(hvv, wd_sh[k][o], oacc[o]);
            }
            const int s0 = s - 63;
            float* op = outrow + (size_t)(s0 + j) * OUTD;
            #pragma unroll
            for (int o = 0; o < OUTD; o++) op[o] = oacc[o];
            __syncthreads();   // epilogue done before slot 0 is overwritten
        } else {
            __syncthreads();   // h_s visible to all threads for step s+1
        }
    }
}

extern "C" void kernel_launch(void* const* d_in, const int* in_sizes, int n_in,
                              void* d_out, int out_size)
{
    (void)in_sizes; (void)n_in; (void)out_size;
    const int*   num1  = (const int*)d_in[0];
    const int*   num2  = (const int*)d_in[1];
    const float* embed = (const float*)d_in[2];
    const float* Wx    = (const float*)d_in[3];
    const float* Wh    = (const float*)d_in[4];
    const float* b     = (const float*)d_in[5];
    const float* Wd    = (const float*)d_in[6];
    const float* bd    = (const float*)d_in[7];
    float* out = (float*)d_out;

    rnn_fused_kernel<<<BB, HH>>>(num1, num2, embed, Wx, Wh, b, Wd, bd, out);
}